// round 7
// baseline (speedup 1.0000x reference)
#include <cuda_runtime.h>
#include <stdint.h>

#define NN 100000
#define NE 600000
#define D 128
#define SCAN_B 1024

// Scratch (device globals -- no runtime allocation allowed)
__device__ __align__(16) float g_msum[(size_t)NN * D];
__device__ __align__(16) float g_h1[(size_t)NN * D];
__device__ __align__(16) float g_h2[(size_t)NN * D];
__device__ int g_cnt[NN];
__device__ int g_fill[NN];
__device__ int g_rowptr[NN + 1];
__device__ int g_col[NE];
__device__ int g_blocksum[128];
__device__ int g_blockoff[128];
__device__ int g_is64;

// ---------------------------------------------------------------------------
// Packed f32x2 helpers (Blackwell FFMA2 -- only reachable via PTX)
// ---------------------------------------------------------------------------
__device__ __forceinline__ void ffma2(unsigned long long& acc,
                                      unsigned long long a,
                                      unsigned long long b) {
    asm("fma.rn.f32x2 %0, %1, %2, %0;" : "+l"(acc) : "l"(a), "l"(b));
}
__device__ __forceinline__ unsigned long long pack2(float lo, float hi) {
    unsigned long long r;
    asm("mov.b64 %0, {%1, %2};" : "=l"(r) : "f"(lo), "f"(hi));
    return r;
}
__device__ __forceinline__ float2 unpack2(unsigned long long v) {
    float lo, hi;
    asm("mov.b64 {%0, %1}, %2;" : "=f"(lo), "=f"(hi) : "l"(v));
    return make_float2(lo, hi);
}

// ---------------------------------------------------------------------------
// Edge-index dtype detection (reference says int64; default JAX yields int32)
// ---------------------------------------------------------------------------
__global__ void detect_kernel(const unsigned int* __restrict__ ei32,
                              int npairs) {
    __shared__ int any;
    if (threadIdx.x == 0) any = 0;
    __syncthreads();
    int found = 0;
    for (int i = threadIdx.x; i < npairs; i += blockDim.x)
        if (ei32[2 * i + 1] != 0u) found = 1;
    if (found) any = 1;   // benign race
    __syncthreads();
    if (threadIdx.x == 0) g_is64 = (any == 0);
}

__device__ __forceinline__ int edge_at(const void* __restrict__ ei, int i) {
    if (g_is64) return (int)((const long long*)ei)[i];
    return ((const int*)ei)[i];
}

// ---------------------------------------------------------------------------
// CSR build: histogram -> block scan -> fill
// ---------------------------------------------------------------------------
__global__ void zero_cnt_kernel(int n) {
    int i = blockIdx.x * blockDim.x + threadIdx.x;
    if (i < n) { g_cnt[i] = 0; g_fill[i] = 0; }
}

__global__ void hist_kernel(const void* __restrict__ ei, int E, int n) {
    int e = blockIdx.x * blockDim.x + threadIdx.x;
    if (e >= E) return;
    unsigned d = min((unsigned)edge_at(ei, E + e), (unsigned)(n - 1));
    atomicAdd(&g_cnt[d], 1);
}

__global__ void __launch_bounds__(SCAN_B) scan1_kernel(int n) {
    __shared__ int sm[SCAN_B];
    int i = blockIdx.x * SCAN_B + threadIdx.x;
    sm[threadIdx.x] = (i < n) ? g_cnt[i] : 0;
    __syncthreads();
    for (int off = SCAN_B / 2; off > 0; off >>= 1) {
        if (threadIdx.x < off) sm[threadIdx.x] += sm[threadIdx.x + off];
        __syncthreads();
    }
    if (threadIdx.x == 0) g_blocksum[blockIdx.x] = sm[0];
}

__global__ void scan2_kernel(int nb, int n, int E) {
    if (threadIdx.x == 0) {
        int run = 0;
        for (int b = 0; b < nb; b++) { g_blockoff[b] = run; run += g_blocksum[b]; }
        g_rowptr[n] = E;
    }
}

__global__ void __launch_bounds__(SCAN_B) scan3_kernel(int n) {
    __shared__ int sm[SCAN_B];
    int i = blockIdx.x * SCAN_B + threadIdx.x;
    int v = (i < n) ? g_cnt[i] : 0;
    sm[threadIdx.x] = v;
    __syncthreads();
    for (int off = 1; off < SCAN_B; off <<= 1) {
        int t = 0;
        if ((int)threadIdx.x >= off) t = sm[threadIdx.x - off];
        __syncthreads();
        if ((int)threadIdx.x >= off) sm[threadIdx.x] += t;
        __syncthreads();
    }
    if (i < n) g_rowptr[i] = g_blockoff[blockIdx.x] + sm[threadIdx.x] - v;
}

__global__ void fill_kernel(const void* __restrict__ ei, int E, int n) {
    int e = blockIdx.x * blockDim.x + threadIdx.x;
    if (e >= E) return;
    unsigned s = min((unsigned)edge_at(ei, e), (unsigned)(n - 1));
    unsigned d = min((unsigned)edge_at(ei, E + e), (unsigned)(n - 1));
    int pos = g_rowptr[d] + atomicAdd(&g_fill[d], 1);
    g_col[pos] = (int)s;
}

// ---------------------------------------------------------------------------
// Gather aggregation: msum[i] = mean over in-neighbors of h[col].
// One warp per node; lane owns 16B. 4-deep software pipeline for MLP.
// ---------------------------------------------------------------------------
template <int SRC>
__global__ void __launch_bounds__(256) agg_kernel(const float* __restrict__ x,
                                                  int n) {
    int tid = blockIdx.x * blockDim.x + threadIdx.x;
    int node = tid >> 5;
    if (node >= n) return;
    int lane = tid & 31;
    const float* h = (SRC == 0) ? x : g_h1;
    int beg = g_rowptr[node], end = g_rowptr[node + 1];
    float4 acc = make_float4(0.f, 0.f, 0.f, 0.f);
    int k = beg;
    for (; k + 4 <= end; k += 4) {
        int c0 = g_col[k + 0], c1 = g_col[k + 1];
        int c2 = g_col[k + 2], c3 = g_col[k + 3];
        float4 v0 = *(const float4*)(h + (size_t)c0 * D + lane * 4);
        float4 v1 = *(const float4*)(h + (size_t)c1 * D + lane * 4);
        float4 v2 = *(const float4*)(h + (size_t)c2 * D + lane * 4);
        float4 v3 = *(const float4*)(h + (size_t)c3 * D + lane * 4);
        acc.x += v0.x + v1.x + v2.x + v3.x;
        acc.y += v0.y + v1.y + v2.y + v3.y;
        acc.z += v0.z + v1.z + v2.z + v3.z;
        acc.w += v0.w + v1.w + v2.w + v3.w;
    }
    for (; k < end; ++k) {
        int c = g_col[k];
        float4 v = *(const float4*)(h + (size_t)c * D + lane * 4);
        acc.x += v.x; acc.y += v.y; acc.z += v.z; acc.w += v.w;
    }
    float sc = 1.f / fmaxf((float)(end - beg), 1.f);
    acc.x *= sc; acc.y *= sc; acc.z *= sc; acc.w *= sc;
    *(float4*)(g_msum + (size_t)node * D + lane * 4) = acc;
}

// ---------------------------------------------------------------------------
// Fused SAGE layer: out = relu( msum @ Wl + bl + h @ Wr )   (msum is mean)
// T=4 nodes/thread, C=16 cols/block (grid.y=8): halves SMEM traffic vs T=2.
// Block covers 1024 nodes x 16 cols; weight slice 128x16 per table in SMEM.
// ---------------------------------------------------------------------------
template <int SRC, int OUT>
__global__ void __launch_bounds__(256) sage_kernel(
    const float* __restrict__ x, const float* __restrict__ Wl,
    const float* __restrict__ bl, const float* __restrict__ Wr, int n) {
    __shared__ float sWl[D * 16];
    __shared__ float sWr[D * 16];
    __shared__ float sb[16];

    const int j0 = blockIdx.y * 16;
    for (int idx = threadIdx.x; idx < D * 16; idx += 256) {
        int k = idx >> 4, jj = idx & 15;
        sWl[idx] = Wl[k * D + j0 + jj];
        sWr[idx] = Wr[k * D + j0 + jj];
    }
    if (threadIdx.x < 16) sb[threadIdx.x] = bl[j0 + threadIdx.x];
    __syncthreads();

    const float* h = (SRC == 0) ? x : g_h1;
    float* out = (OUT == 1) ? g_h1 : g_h2;

    int nd[4];
    const float4* mp[4];
    const float4* hp[4];
#pragma unroll
    for (int i = 0; i < 4; i++) {
        nd[i] = blockIdx.x * 1024 + threadIdx.x + i * 256;
        int c = min(nd[i], n - 1);
        mp[i] = (const float4*)(g_msum + (size_t)c * D);
        hp[i] = (const float4*)(h + (size_t)c * D);
    }

    // acc[i][p]: node i, col pair p (cols 2p, 2p+1)
    unsigned long long acc[4][8];
#pragma unroll
    for (int p = 0; p < 8; p++) {
        unsigned long long b = pack2(sb[2 * p], sb[2 * p + 1]);
#pragma unroll
        for (int i = 0; i < 4; i++) acc[i][p] = b;
    }

    for (int k4 = 0; k4 < 32; ++k4) {
        float am[4][4], ar[4][4];
#pragma unroll
        for (int i = 0; i < 4; i++) {
            float4 m = mp[i][k4];
            float4 q = hp[i][k4];
            am[i][0] = m.x; am[i][1] = m.y; am[i][2] = m.z; am[i][3] = m.w;
            ar[i][0] = q.x; ar[i][1] = q.y; ar[i][2] = q.z; ar[i][3] = q.w;
        }
#pragma unroll
        for (int kk = 0; kk < 4; ++kk) {
            const int kbase = (k4 * 4 + kk) * 16;
            ulonglong2 wlA = *(const ulonglong2*)&sWl[kbase + 0];
            ulonglong2 wlB = *(const ulonglong2*)&sWl[kbase + 4];
            ulonglong2 wlC = *(const ulonglong2*)&sWl[kbase + 8];
            ulonglong2 wlD = *(const ulonglong2*)&sWl[kbase + 12];
            ulonglong2 wrA = *(const ulonglong2*)&sWr[kbase + 0];
            ulonglong2 wrB = *(const ulonglong2*)&sWr[kbase + 4];
            ulonglong2 wrC = *(const ulonglong2*)&sWr[kbase + 8];
            ulonglong2 wrD = *(const ulonglong2*)&sWr[kbase + 12];
#pragma unroll
            for (int i = 0; i < 4; i++) {
                unsigned long long pa = pack2(am[i][kk], am[i][kk]);
                unsigned long long pr = pack2(ar[i][kk], ar[i][kk]);
                ffma2(acc[i][0], pa, wlA.x);
                ffma2(acc[i][1], pa, wlA.y);
                ffma2(acc[i][2], pa, wlB.x);
                ffma2(acc[i][3], pa, wlB.y);
                ffma2(acc[i][4], pa, wlC.x);
                ffma2(acc[i][5], pa, wlC.y);
                ffma2(acc[i][6], pa, wlD.x);
                ffma2(acc[i][7], pa, wlD.y);
                ffma2(acc[i][0], pr, wrA.x);
                ffma2(acc[i][1], pr, wrA.y);
                ffma2(acc[i][2], pr, wrB.x);
                ffma2(acc[i][3], pr, wrB.y);
                ffma2(acc[i][4], pr, wrC.x);
                ffma2(acc[i][5], pr, wrC.y);
                ffma2(acc[i][6], pr, wrD.x);
                ffma2(acc[i][7], pr, wrD.y);
            }
        }
    }

#pragma unroll
    for (int i = 0; i < 4; i++) {
        if (nd[i] < n) {
            float4* o = (float4*)(out + (size_t)nd[i] * D + j0);
#pragma unroll
            for (int q = 0; q < 4; ++q) {
                float2 a = unpack2(acc[i][q * 2 + 0]);
                float2 b = unpack2(acc[i][q * 2 + 1]);
                o[q] = make_float4(fmaxf(a.x, 0.f), fmaxf(a.y, 0.f),
                                   fmaxf(b.x, 0.f), fmaxf(b.y, 0.f));
            }
        }
    }
}

// ---------------------------------------------------------------------------
// lin0: t = relu(g_h2 @ W0 + b0), stored to g_msum[node*64 + col]
// T=4 nodes/thread, C=16 cols/block (grid.y=4).
// ---------------------------------------------------------------------------
__global__ void __launch_bounds__(256) lin0_kernel(
    const float* __restrict__ W0, const float* __restrict__ b0, int n) {
    __shared__ float sW0[D * 16];
    __shared__ float sb[16];

    const int j0 = blockIdx.y * 16;
    for (int idx = threadIdx.x; idx < D * 16; idx += 256) {
        int k = idx >> 4, jj = idx & 15;
        sW0[idx] = W0[k * 64 + j0 + jj];
    }
    if (threadIdx.x < 16) sb[threadIdx.x] = b0[j0 + threadIdx.x];
    __syncthreads();

    int nd[4];
    const float4* hp[4];
#pragma unroll
    for (int i = 0; i < 4; i++) {
        nd[i] = blockIdx.x * 1024 + threadIdx.x + i * 256;
        int c = min(nd[i], n - 1);
        hp[i] = (const float4*)(g_h2 + (size_t)c * D);
    }

    unsigned long long acc[4][8];
#pragma unroll
    for (int p = 0; p < 8; p++) {
        unsigned long long b = pack2(sb[2 * p], sb[2 * p + 1]);
#pragma unroll
        for (int i = 0; i < 4; i++) acc[i][p] = b;
    }

    for (int k4 = 0; k4 < 32; ++k4) {
        float ar[4][4];
#pragma unroll
        for (int i = 0; i < 4; i++) {
            float4 q = hp[i][k4];
            ar[i][0] = q.x; ar[i][1] = q.y; ar[i][2] = q.z; ar[i][3] = q.w;
        }
#pragma unroll
        for (int kk = 0; kk < 4; ++kk) {
            const int kbase = (k4 * 4 + kk) * 16;
            ulonglong2 wA = *(const ulonglong2*)&sW0[kbase + 0];
            ulonglong2 wB = *(const ulonglong2*)&sW0[kbase + 4];
            ulonglong2 wC = *(const ulonglong2*)&sW0[kbase + 8];
            ulonglong2 wD = *(const ulonglong2*)&sW0[kbase + 12];
#pragma unroll
            for (int i = 0; i < 4; i++) {
                unsigned long long pr = pack2(ar[i][kk], ar[i][kk]);
                ffma2(acc[i][0], pr, wA.x);
                ffma2(acc[i][1], pr, wA.y);
                ffma2(acc[i][2], pr, wB.x);
                ffma2(acc[i][3], pr, wB.y);
                ffma2(acc[i][4], pr, wC.x);
                ffma2(acc[i][5], pr, wC.y);
                ffma2(acc[i][6], pr, wD.x);
                ffma2(acc[i][7], pr, wD.y);
            }
        }
    }

#pragma unroll
    for (int i = 0; i < 4; i++) {
        if (nd[i] < n) {
            float4* o = (float4*)(g_msum + (size_t)nd[i] * 64 + j0);
#pragma unroll
            for (int q = 0; q < 4; ++q) {
                float2 a = unpack2(acc[i][q * 2 + 0]);
                float2 b = unpack2(acc[i][q * 2 + 1]);
                o[q] = make_float4(fmaxf(a.x, 0.f), fmaxf(a.y, 0.f),
                                   fmaxf(b.x, 0.f), fmaxf(b.y, 0.f));
            }
        }
    }
}

// ---------------------------------------------------------------------------
// lin1: out = relu(t @ W1 + b1), t = g_msum[node*64 .. +64]
// ---------------------------------------------------------------------------
__global__ void __launch_bounds__(256) lin1_kernel(
    const float* __restrict__ W1, const float* __restrict__ b1,
    float* __restrict__ out, int n) {
    __shared__ float sW1[64 * 8];
    __shared__ float sb1[8];
    for (int idx = threadIdx.x; idx < 64 * 8; idx += 256) sW1[idx] = W1[idx];
    if (threadIdx.x < 8) sb1[threadIdx.x] = b1[threadIdx.x];
    __syncthreads();

    const int n0 = blockIdx.x * 256 + threadIdx.x;
    const int c0 = min(n0, n - 1);
    const float4* tp = (const float4*)(g_msum + (size_t)c0 * 64);

    unsigned long long o2[4];
#pragma unroll
    for (int p = 0; p < 4; p++) o2[p] = pack2(sb1[2 * p], sb1[2 * p + 1]);

#pragma unroll
    for (int k4 = 0; k4 < 16; ++k4) {
        float4 tv = tp[k4];
        float r[4] = {tv.x, tv.y, tv.z, tv.w};
#pragma unroll
        for (int kk = 0; kk < 4; ++kk) {
            const int kbase = (k4 * 4 + kk) * 8;
            ulonglong2 wA = *(const ulonglong2*)&sW1[kbase + 0];
            ulonglong2 wB = *(const ulonglong2*)&sW1[kbase + 4];
            unsigned long long pr = pack2(r[kk], r[kk]);
            ffma2(o2[0], pr, wA.x);
            ffma2(o2[1], pr, wA.y);
            ffma2(o2[2], pr, wB.x);
            ffma2(o2[3], pr, wB.y);
        }
    }

    if (n0 < n) {
        float4* op = (float4*)(out + (size_t)n0 * 8);
        float2 a = unpack2(o2[0]), b = unpack2(o2[1]);
        float2 c = unpack2(o2[2]), dd = unpack2(o2[3]);
        op[0] = make_float4(fmaxf(a.x, 0.f), fmaxf(a.y, 0.f),
                            fmaxf(b.x, 0.f), fmaxf(b.y, 0.f));
        op[1] = make_float4(fmaxf(c.x, 0.f), fmaxf(c.y, 0.f),
                            fmaxf(dd.x, 0.f), fmaxf(dd.y, 0.f));
    }
}

// ---------------------------------------------------------------------------
// Launcher (no allocation, graph-capturable)
// ---------------------------------------------------------------------------
extern "C" void kernel_launch(void* const* d_in, const int* in_sizes, int n_in,
                              void* d_out, int out_size) {
    const float* x    = (const float*)d_in[0];
    const void*  ei   = d_in[1];
    const float* s0Wl = (const float*)d_in[2];
    const float* s0bl = (const float*)d_in[3];
    const float* s0Wr = (const float*)d_in[4];
    const float* s1Wl = (const float*)d_in[5];
    const float* s1bl = (const float*)d_in[6];
    const float* s1Wr = (const float*)d_in[7];
    const float* l0W  = (const float*)d_in[8];
    const float* l0b  = (const float*)d_in[9];
    const float* l1W  = (const float*)d_in[10];
    const float* l1b  = (const float*)d_in[11];
    float* out = (float*)d_out;

    const int N = in_sizes[0] / D;
    const int E = in_sizes[1] / 2;
    const int NB = (N + SCAN_B - 1) / SCAN_B;

    detect_kernel<<<1, 256>>>((const unsigned int*)ei, 2048);

    // CSR build (once per launch; shared by both layers)
    zero_cnt_kernel<<<(N + 255) / 256, 256>>>(N);
    hist_kernel<<<(E + 255) / 256, 256>>>(ei, E, N);
    scan1_kernel<<<NB, SCAN_B>>>(N);
    scan2_kernel<<<1, 32>>>(NB, N, E);
    scan3_kernel<<<NB, SCAN_B>>>(N);
    fill_kernel<<<(E + 255) / 256, 256>>>(ei, E, N);

    const int agg_blocks = (int)(((long long)N * 32 + 255) / 256);
    dim3 sgrid((N + 1023) / 1024, 8);
    dim3 lgrid((N + 1023) / 1024, 4);

    // layer 0
    agg_kernel<0><<<agg_blocks, 256>>>(x, N);
    sage_kernel<0, 1><<<sgrid, 256>>>(x, s0Wl, s0bl, s0Wr, N);

    // layer 1
    agg_kernel<1><<<agg_blocks, 256>>>(x, N);
    sage_kernel<1, 2><<<sgrid, 256>>>(x, s1Wl, s1bl, s1Wr, N);

    // MLP head
    lin0_kernel<<<lgrid, 256>>>(l0W, l0b, N);
    lin1_kernel<<<(N + 255) / 256, 256>>>(l1W, l1b, out, N);
}

// round 8
// speedup vs baseline: 1.3054x; 1.3054x over previous
#include <cuda_runtime.h>
#include <stdint.h>

#define NN 100000
#define NE 600000
#define D 128
#define SCAN_B 1024

// Scratch (device globals -- no runtime allocation allowed)
__device__ __align__(16) float g_msum[(size_t)NN * D];
__device__ __align__(16) float g_h1[(size_t)NN * D];
__device__ __align__(16) float g_h2[(size_t)NN * D];
__device__ int g_cnt[NN];
__device__ int g_fill[NN];
__device__ int g_rowptr[NN + 1];
__device__ int g_col[NE];
__device__ int g_blocksum[128];
__device__ int g_blockoff[128];
__device__ int g_is64;

// ---------------------------------------------------------------------------
// Packed f32x2 helpers (Blackwell FFMA2 -- only reachable via PTX)
// ---------------------------------------------------------------------------
__device__ __forceinline__ void ffma2(unsigned long long& acc,
                                      unsigned long long a,
                                      unsigned long long b) {
    asm("fma.rn.f32x2 %0, %1, %2, %0;" : "+l"(acc) : "l"(a), "l"(b));
}
__device__ __forceinline__ unsigned long long pack2(float lo, float hi) {
    unsigned long long r;
    asm("mov.b64 %0, {%1, %2};" : "=l"(r) : "f"(lo), "f"(hi));
    return r;
}
__device__ __forceinline__ float2 unpack2(unsigned long long v) {
    float lo, hi;
    asm("mov.b64 {%0, %1}, %2;" : "=f"(lo), "=f"(hi) : "l"(v));
    return make_float2(lo, hi);
}

// ---------------------------------------------------------------------------
// Edge-index dtype detection (reference says int64; default JAX yields int32)
// ---------------------------------------------------------------------------
__global__ void detect_kernel(const unsigned int* __restrict__ ei32,
                              int npairs) {
    __shared__ int any;
    if (threadIdx.x == 0) any = 0;
    __syncthreads();
    int found = 0;
    for (int i = threadIdx.x; i < npairs; i += blockDim.x)
        if (ei32[2 * i + 1] != 0u) found = 1;
    if (found) any = 1;   // benign race
    __syncthreads();
    if (threadIdx.x == 0) g_is64 = (any == 0);
}

__device__ __forceinline__ int edge_at(const void* __restrict__ ei, int i) {
    if (g_is64) return (int)((const long long*)ei)[i];
    return ((const int*)ei)[i];
}

// ---------------------------------------------------------------------------
// CSR build: histogram -> block scan -> fill
// ---------------------------------------------------------------------------
__global__ void zero_cnt_kernel(int n) {
    int i = blockIdx.x * blockDim.x + threadIdx.x;
    if (i < n) { g_cnt[i] = 0; g_fill[i] = 0; }
}

__global__ void hist_kernel(const void* __restrict__ ei, int E, int n) {
    int e = blockIdx.x * blockDim.x + threadIdx.x;
    if (e >= E) return;
    unsigned d = min((unsigned)edge_at(ei, E + e), (unsigned)(n - 1));
    atomicAdd(&g_cnt[d], 1);
}

__global__ void __launch_bounds__(SCAN_B) scan1_kernel(int n) {
    __shared__ int sm[SCAN_B];
    int i = blockIdx.x * SCAN_B + threadIdx.x;
    sm[threadIdx.x] = (i < n) ? g_cnt[i] : 0;
    __syncthreads();
    for (int off = SCAN_B / 2; off > 0; off >>= 1) {
        if (threadIdx.x < off) sm[threadIdx.x] += sm[threadIdx.x + off];
        __syncthreads();
    }
    if (threadIdx.x == 0) g_blocksum[blockIdx.x] = sm[0];
}

__global__ void scan2_kernel(int nb, int n, int E) {
    if (threadIdx.x == 0) {
        int run = 0;
        for (int b = 0; b < nb; b++) { g_blockoff[b] = run; run += g_blocksum[b]; }
        g_rowptr[n] = E;
    }
}

__global__ void __launch_bounds__(SCAN_B) scan3_kernel(int n) {
    __shared__ int sm[SCAN_B];
    int i = blockIdx.x * SCAN_B + threadIdx.x;
    int v = (i < n) ? g_cnt[i] : 0;
    sm[threadIdx.x] = v;
    __syncthreads();
    for (int off = 1; off < SCAN_B; off <<= 1) {
        int t = 0;
        if ((int)threadIdx.x >= off) t = sm[threadIdx.x - off];
        __syncthreads();
        if ((int)threadIdx.x >= off) sm[threadIdx.x] += t;
        __syncthreads();
    }
    if (i < n) g_rowptr[i] = g_blockoff[blockIdx.x] + sm[threadIdx.x] - v;
}

__global__ void fill_kernel(const void* __restrict__ ei, int E, int n) {
    int e = blockIdx.x * blockDim.x + threadIdx.x;
    if (e >= E) return;
    unsigned s = min((unsigned)edge_at(ei, e), (unsigned)(n - 1));
    unsigned d = min((unsigned)edge_at(ei, E + e), (unsigned)(n - 1));
    int pos = g_rowptr[d] + atomicAdd(&g_fill[d], 1);
    g_col[pos] = (int)s;
}

// ---------------------------------------------------------------------------
// Gather aggregation: msum[i] = mean over in-neighbors of h[col].
// One warp per node; lane owns 16B. 4-deep unroll for MLP.
// ---------------------------------------------------------------------------
template <int SRC>
__global__ void __launch_bounds__(256) agg_kernel(const float* __restrict__ x,
                                                  int n) {
    int tid = blockIdx.x * blockDim.x + threadIdx.x;
    int node = tid >> 5;
    if (node >= n) return;
    int lane = tid & 31;
    const float* h = (SRC == 0) ? x : g_h1;
    int beg = g_rowptr[node], end = g_rowptr[node + 1];
    float4 acc = make_float4(0.f, 0.f, 0.f, 0.f);
    int k = beg;
    for (; k + 4 <= end; k += 4) {
        int c0 = g_col[k + 0], c1 = g_col[k + 1];
        int c2 = g_col[k + 2], c3 = g_col[k + 3];
        float4 v0 = *(const float4*)(h + (size_t)c0 * D + lane * 4);
        float4 v1 = *(const float4*)(h + (size_t)c1 * D + lane * 4);
        float4 v2 = *(const float4*)(h + (size_t)c2 * D + lane * 4);
        float4 v3 = *(const float4*)(h + (size_t)c3 * D + lane * 4);
        acc.x += v0.x + v1.x + v2.x + v3.x;
        acc.y += v0.y + v1.y + v2.y + v3.y;
        acc.z += v0.z + v1.z + v2.z + v3.z;
        acc.w += v0.w + v1.w + v2.w + v3.w;
    }
    for (; k < end; ++k) {
        int c = g_col[k];
        float4 v = *(const float4*)(h + (size_t)c * D + lane * 4);
        acc.x += v.x; acc.y += v.y; acc.z += v.z; acc.w += v.w;
    }
    float sc = 1.f / fmaxf((float)(end - beg), 1.f);
    acc.x *= sc; acc.y *= sc; acc.z *= sc; acc.w *= sc;
    *(float4*)(g_msum + (size_t)node * D + lane * 4) = acc;
}

// ---------------------------------------------------------------------------
// Fused SAGE layer: out = relu( msum @ Wl + bl + h @ Wr )
// Tm=4 nodes/thread, C=32 cols/block, grid.y=4 (same activation traffic as
// the 719us config, half the SMEM weight traffic per node).
// ---------------------------------------------------------------------------
template <int SRC, int OUT>
__global__ void __launch_bounds__(256) sage_kernel(
    const float* __restrict__ x, const float* __restrict__ Wl,
    const float* __restrict__ bl, const float* __restrict__ Wr, int n) {
    __shared__ float sWl[D * 32];
    __shared__ float sWr[D * 32];
    __shared__ float sb[32];

    const int j0 = blockIdx.y * 32;
    for (int idx = threadIdx.x; idx < D * 32; idx += 256) {
        int k = idx >> 5, jj = idx & 31;
        sWl[idx] = Wl[k * D + j0 + jj];
        sWr[idx] = Wr[k * D + j0 + jj];
    }
    if (threadIdx.x < 32) sb[threadIdx.x] = bl[j0 + threadIdx.x];
    __syncthreads();

    const float* h = (SRC == 0) ? x : g_h1;
    float* out = (OUT == 1) ? g_h1 : g_h2;

    int nd[4];
    const float4* mp[4];
    const float4* hp[4];
#pragma unroll
    for (int i = 0; i < 4; i++) {
        nd[i] = blockIdx.x * 1024 + threadIdx.x + i * 256;
        int c = min(nd[i], n - 1);
        mp[i] = (const float4*)(g_msum + (size_t)c * D);
        hp[i] = (const float4*)(h + (size_t)c * D);
    }

    // acc[i][p]: node i, col pair p (cols 2p, 2p+1); 16 pairs = 32 cols
    unsigned long long acc[4][16];
#pragma unroll
    for (int p = 0; p < 16; p++) {
        unsigned long long b = pack2(sb[2 * p], sb[2 * p + 1]);
#pragma unroll
        for (int i = 0; i < 4; i++) acc[i][p] = b;
    }

    for (int k4 = 0; k4 < 32; ++k4) {
        float am[4][4], ar[4][4];
#pragma unroll
        for (int i = 0; i < 4; i++) {
            float4 m = mp[i][k4];
            float4 q = hp[i][k4];
            am[i][0] = m.x; am[i][1] = m.y; am[i][2] = m.z; am[i][3] = m.w;
            ar[i][0] = q.x; ar[i][1] = q.y; ar[i][2] = q.z; ar[i][3] = q.w;
        }
#pragma unroll
        for (int kk = 0; kk < 4; ++kk) {
            const int kbase = (k4 * 4 + kk) * 32;
            // half 1: col pairs 0..7
            {
                ulonglong2 wl0 = *(const ulonglong2*)&sWl[kbase + 0];
                ulonglong2 wl1 = *(const ulonglong2*)&sWl[kbase + 4];
                ulonglong2 wl2 = *(const ulonglong2*)&sWl[kbase + 8];
                ulonglong2 wl3 = *(const ulonglong2*)&sWl[kbase + 12];
                ulonglong2 wr0 = *(const ulonglong2*)&sWr[kbase + 0];
                ulonglong2 wr1 = *(const ulonglong2*)&sWr[kbase + 4];
                ulonglong2 wr2 = *(const ulonglong2*)&sWr[kbase + 8];
                ulonglong2 wr3 = *(const ulonglong2*)&sWr[kbase + 12];
#pragma unroll
                for (int i = 0; i < 4; i++) {
                    unsigned long long pa = pack2(am[i][kk], am[i][kk]);
                    unsigned long long pr = pack2(ar[i][kk], ar[i][kk]);
                    ffma2(acc[i][0], pa, wl0.x);
                    ffma2(acc[i][1], pa, wl0.y);
                    ffma2(acc[i][2], pa, wl1.x);
                    ffma2(acc[i][3], pa, wl1.y);
                    ffma2(acc[i][4], pa, wl2.x);
                    ffma2(acc[i][5], pa, wl2.y);
                    ffma2(acc[i][6], pa, wl3.x);
                    ffma2(acc[i][7], pa, wl3.y);
                    ffma2(acc[i][0], pr, wr0.x);
                    ffma2(acc[i][1], pr, wr0.y);
                    ffma2(acc[i][2], pr, wr1.x);
                    ffma2(acc[i][3], pr, wr1.y);
                    ffma2(acc[i][4], pr, wr2.x);
                    ffma2(acc[i][5], pr, wr2.y);
                    ffma2(acc[i][6], pr, wr3.x);
                    ffma2(acc[i][7], pr, wr3.y);
                }
            }
            // half 2: col pairs 8..15
            {
                ulonglong2 wl0 = *(const ulonglong2*)&sWl[kbase + 16];
                ulonglong2 wl1 = *(const ulonglong2*)&sWl[kbase + 20];
                ulonglong2 wl2 = *(const ulonglong2*)&sWl[kbase + 24];
                ulonglong2 wl3 = *(const ulonglong2*)&sWl[kbase + 28];
                ulonglong2 wr0 = *(const ulonglong2*)&sWr[kbase + 16];
                ulonglong2 wr1 = *(const ulonglong2*)&sWr[kbase + 20];
                ulonglong2 wr2 = *(const ulonglong2*)&sWr[kbase + 24];
                ulonglong2 wr3 = *(const ulonglong2*)&sWr[kbase + 28];
#pragma unroll
                for (int i = 0; i < 4; i++) {
                    unsigned long long pa = pack2(am[i][kk], am[i][kk]);
                    unsigned long long pr = pack2(ar[i][kk], ar[i][kk]);
                    ffma2(acc[i][8],  pa, wl0.x);
                    ffma2(acc[i][9],  pa, wl0.y);
                    ffma2(acc[i][10], pa, wl1.x);
                    ffma2(acc[i][11], pa, wl1.y);
                    ffma2(acc[i][12], pa, wl2.x);
                    ffma2(acc[i][13], pa, wl2.y);
                    ffma2(acc[i][14], pa, wl3.x);
                    ffma2(acc[i][15], pa, wl3.y);
                    ffma2(acc[i][8],  pr, wr0.x);
                    ffma2(acc[i][9],  pr, wr0.y);
                    ffma2(acc[i][10], pr, wr1.x);
                    ffma2(acc[i][11], pr, wr1.y);
                    ffma2(acc[i][12], pr, wr2.x);
                    ffma2(acc[i][13], pr, wr2.y);
                    ffma2(acc[i][14], pr, wr3.x);
                    ffma2(acc[i][15], pr, wr3.y);
                }
            }
        }
    }

#pragma unroll
    for (int i = 0; i < 4; i++) {
        if (nd[i] < n) {
            float4* o = (float4*)(out + (size_t)nd[i] * D + j0);
#pragma unroll
            for (int q = 0; q < 8; ++q) {
                float2 a = unpack2(acc[i][q * 2 + 0]);
                float2 b = unpack2(acc[i][q * 2 + 1]);
                o[q] = make_float4(fmaxf(a.x, 0.f), fmaxf(a.y, 0.f),
                                   fmaxf(b.x, 0.f), fmaxf(b.y, 0.f));
            }
        }
    }
}

// ---------------------------------------------------------------------------
// lin0: t = relu(g_h2 @ W0 + b0) -> g_msum[node*64 + col]
// Tm=4 nodes/thread, C=32 cols/block, grid.y=2.
// ---------------------------------------------------------------------------
__global__ void __launch_bounds__(256) lin0_kernel(
    const float* __restrict__ W0, const float* __restrict__ b0, int n) {
    __shared__ float sW0[D * 32];
    __shared__ float sb[32];

    const int j0 = blockIdx.y * 32;
    for (int idx = threadIdx.x; idx < D * 32; idx += 256) {
        int k = idx >> 5, jj = idx & 31;
        sW0[idx] = W0[k * 64 + j0 + jj];
    }
    if (threadIdx.x < 32) sb[threadIdx.x] = b0[j0 + threadIdx.x];
    __syncthreads();

    int nd[4];
    const float4* hp[4];
#pragma unroll
    for (int i = 0; i < 4; i++) {
        nd[i] = blockIdx.x * 1024 + threadIdx.x + i * 256;
        int c = min(nd[i], n - 1);
        hp[i] = (const float4*)(g_h2 + (size_t)c * D);
    }

    unsigned long long acc[4][16];
#pragma unroll
    for (int p = 0; p < 16; p++) {
        unsigned long long b = pack2(sb[2 * p], sb[2 * p + 1]);
#pragma unroll
        for (int i = 0; i < 4; i++) acc[i][p] = b;
    }

    for (int k4 = 0; k4 < 32; ++k4) {
        float ar[4][4];
#pragma unroll
        for (int i = 0; i < 4; i++) {
            float4 q = hp[i][k4];
            ar[i][0] = q.x; ar[i][1] = q.y; ar[i][2] = q.z; ar[i][3] = q.w;
        }
#pragma unroll
        for (int kk = 0; kk < 4; ++kk) {
            const int kbase = (k4 * 4 + kk) * 32;
            ulonglong2 w0 = *(const ulonglong2*)&sW0[kbase + 0];
            ulonglong2 w1 = *(const ulonglong2*)&sW0[kbase + 4];
            ulonglong2 w2 = *(const ulonglong2*)&sW0[kbase + 8];
            ulonglong2 w3 = *(const ulonglong2*)&sW0[kbase + 12];
            ulonglong2 w4 = *(const ulonglong2*)&sW0[kbase + 16];
            ulonglong2 w5 = *(const ulonglong2*)&sW0[kbase + 20];
            ulonglong2 w6 = *(const ulonglong2*)&sW0[kbase + 24];
            ulonglong2 w7 = *(const ulonglong2*)&sW0[kbase + 28];
#pragma unroll
            for (int i = 0; i < 4; i++) {
                unsigned long long pr = pack2(ar[i][kk], ar[i][kk]);
                ffma2(acc[i][0],  pr, w0.x);
                ffma2(acc[i][1],  pr, w0.y);
                ffma2(acc[i][2],  pr, w1.x);
                ffma2(acc[i][3],  pr, w1.y);
                ffma2(acc[i][4],  pr, w2.x);
                ffma2(acc[i][5],  pr, w2.y);
                ffma2(acc[i][6],  pr, w3.x);
                ffma2(acc[i][7],  pr, w3.y);
                ffma2(acc[i][8],  pr, w4.x);
                ffma2(acc[i][9],  pr, w4.y);
                ffma2(acc[i][10], pr, w5.x);
                ffma2(acc[i][11], pr, w5.y);
                ffma2(acc[i][12], pr, w6.x);
                ffma2(acc[i][13], pr, w6.y);
                ffma2(acc[i][14], pr, w7.x);
                ffma2(acc[i][15], pr, w7.y);
            }
        }
    }

#pragma unroll
    for (int i = 0; i < 4; i++) {
        if (nd[i] < n) {
            float4* o = (float4*)(g_msum + (size_t)nd[i] * 64 + j0);
#pragma unroll
            for (int q = 0; q < 8; ++q) {
                float2 a = unpack2(acc[i][q * 2 + 0]);
                float2 b = unpack2(acc[i][q * 2 + 1]);
                o[q] = make_float4(fmaxf(a.x, 0.f), fmaxf(a.y, 0.f),
                                   fmaxf(b.x, 0.f), fmaxf(b.y, 0.f));
            }
        }
    }
}

// ---------------------------------------------------------------------------
// lin1: out = relu(t @ W1 + b1), t = g_msum[node*64 .. +64]
// ---------------------------------------------------------------------------
__global__ void __launch_bounds__(256) lin1_kernel(
    const float* __restrict__ W1, const float* __restrict__ b1,
    float* __restrict__ out, int n) {
    __shared__ float sW1[64 * 8];
    __shared__ float sb1[8];
    for (int idx = threadIdx.x; idx < 64 * 8; idx += 256) sW1[idx] = W1[idx];
    if (threadIdx.x < 8) sb1[threadIdx.x] = b1[threadIdx.x];
    __syncthreads();

    const int n0 = blockIdx.x * 256 + threadIdx.x;
    const int c0 = min(n0, n - 1);
    const float4* tp = (const float4*)(g_msum + (size_t)c0 * 64);

    unsigned long long o2[4];
#pragma unroll
    for (int p = 0; p < 4; p++) o2[p] = pack2(sb1[2 * p], sb1[2 * p + 1]);

#pragma unroll
    for (int k4 = 0; k4 < 16; ++k4) {
        float4 tv = tp[k4];
        float r[4] = {tv.x, tv.y, tv.z, tv.w};
#pragma unroll
        for (int kk = 0; kk < 4; ++kk) {
            const int kbase = (k4 * 4 + kk) * 8;
            ulonglong2 wA = *(const ulonglong2*)&sW1[kbase + 0];
            ulonglong2 wB = *(const ulonglong2*)&sW1[kbase + 4];
            unsigned long long pr = pack2(r[kk], r[kk]);
            ffma2(o2[0], pr, wA.x);
            ffma2(o2[1], pr, wA.y);
            ffma2(o2[2], pr, wB.x);
            ffma2(o2[3], pr, wB.y);
        }
    }

    if (n0 < n) {
        float4* op = (float4*)(out + (size_t)n0 * 8);
        float2 a = unpack2(o2[0]), b = unpack2(o2[1]);
        float2 c = unpack2(o2[2]), dd = unpack2(o2[3]);
        op[0] = make_float4(fmaxf(a.x, 0.f), fmaxf(a.y, 0.f),
                            fmaxf(b.x, 0.f), fmaxf(b.y, 0.f));
        op[1] = make_float4(fmaxf(c.x, 0.f), fmaxf(c.y, 0.f),
                            fmaxf(dd.x, 0.f), fmaxf(dd.y, 0.f));
    }
}

// ---------------------------------------------------------------------------
// Launcher (no allocation, graph-capturable)
// ---------------------------------------------------------------------------
extern "C" void kernel_launch(void* const* d_in, const int* in_sizes, int n_in,
                              void* d_out, int out_size) {
    const float* x    = (const float*)d_in[0];
    const void*  ei   = d_in[1];
    const float* s0Wl = (const float*)d_in[2];
    const float* s0bl = (const float*)d_in[3];
    const float* s0Wr = (const float*)d_in[4];
    const float* s1Wl = (const float*)d_in[5];
    const float* s1bl = (const float*)d_in[6];
    const float* s1Wr = (const float*)d_in[7];
    const float* l0W  = (const float*)d_in[8];
    const float* l0b  = (const float*)d_in[9];
    const float* l1W  = (const float*)d_in[10];
    const float* l1b  = (const float*)d_in[11];
    float* out = (float*)d_out;

    const int N = in_sizes[0] / D;
    const int E = in_sizes[1] / 2;
    const int NB = (N + SCAN_B - 1) / SCAN_B;

    detect_kernel<<<1, 256>>>((const unsigned int*)ei, 2048);

    // CSR build (once per launch; shared by both layers)
    zero_cnt_kernel<<<(N + 255) / 256, 256>>>(N);
    hist_kernel<<<(E + 255) / 256, 256>>>(ei, E, N);
    scan1_kernel<<<NB, SCAN_B>>>(N);
    scan2_kernel<<<1, 32>>>(NB, N, E);
    scan3_kernel<<<NB, SCAN_B>>>(N);
    fill_kernel<<<(E + 255) / 256, 256>>>(ei, E, N);

    const int agg_blocks = (int)(((long long)N * 32 + 255) / 256);
    dim3 sgrid((N + 1023) / 1024, 4);
    dim3 lgrid((N + 1023) / 1024, 2);

    // layer 0
    agg_kernel<0><<<agg_blocks, 256>>>(x, N);
    sage_kernel<0, 1><<<sgrid, 256>>>(x, s0Wl, s0bl, s0Wr, N);

    // layer 1
    agg_kernel<1><<<agg_blocks, 256>>>(x, N);
    sage_kernel<1, 2><<<sgrid, 256>>>(x, s1Wl, s1bl, s1Wr, N);

    // MLP head
    lin0_kernel<<<lgrid, 256>>>(l0W, l0b, N);
    lin1_kernel<<<(N + 255) / 256, 256>>>(l1W, l1b, out, N);
}

// round 9
// speedup vs baseline: 1.6017x; 1.2270x over previous
#include <cuda_runtime.h>
#include <stdint.h>

#define NN 100000
#define NE 600000
#define D 128
#define SCAN_B 1024

#define SM_K 64
#define SM_PITCH 136
#define SM_BYTES (2 * SM_K * SM_PITCH * 4)   // hi + lo planes, 69632 B

// Scratch (device globals -- no runtime allocation allowed)
__device__ __align__(16) float g_msum[(size_t)NN * D];
__device__ __align__(16) float g_h1[(size_t)NN * D];
__device__ __align__(16) float g_h2[(size_t)NN * D];
__device__ int g_cnt[NN];
__device__ int g_fill[NN];
__device__ int g_rowptr[NN + 1];
__device__ int g_col[NE];
__device__ int g_blocksum[128];
__device__ int g_blockoff[128];
__device__ int g_is64;

// ---------------------------------------------------------------------------
// Packed f32x2 helpers (for the SIMT lin kernels)
// ---------------------------------------------------------------------------
__device__ __forceinline__ void ffma2(unsigned long long& acc,
                                      unsigned long long a,
                                      unsigned long long b) {
    asm("fma.rn.f32x2 %0, %1, %2, %0;" : "+l"(acc) : "l"(a), "l"(b));
}
__device__ __forceinline__ unsigned long long pack2(float lo, float hi) {
    unsigned long long r;
    asm("mov.b64 %0, {%1, %2};" : "=l"(r) : "f"(lo), "f"(hi));
    return r;
}
__device__ __forceinline__ float2 unpack2(unsigned long long v) {
    float lo, hi;
    asm("mov.b64 {%0, %1}, %2;" : "=f"(lo), "=f"(hi) : "l"(v));
    return make_float2(lo, hi);
}

// ---------------------------------------------------------------------------
// tf32 helpers
// ---------------------------------------------------------------------------
__device__ __forceinline__ uint32_t f2tf32(float f) {
    uint32_t r;
    asm("cvt.rna.tf32.f32 %0, %1;" : "=r"(r) : "f"(f));
    return r;
}
__device__ __forceinline__ void mma_tf32(float& c0, float& c1, float& c2,
                                         float& c3, uint32_t a0, uint32_t a1,
                                         uint32_t a2, uint32_t a3, uint32_t b0,
                                         uint32_t b1) {
    asm("mma.sync.aligned.m16n8k8.row.col.f32.tf32.tf32.f32 "
        "{%0,%1,%2,%3},{%4,%5,%6,%7},{%8,%9},{%0,%1,%2,%3};"
        : "+f"(c0), "+f"(c1), "+f"(c2), "+f"(c3)
        : "r"(a0), "r"(a1), "r"(a2), "r"(a3), "r"(b0), "r"(b1));
}

// ---------------------------------------------------------------------------
// Edge-index dtype detection (reference says int64; default JAX yields int32)
// ---------------------------------------------------------------------------
__global__ void detect_kernel(const unsigned int* __restrict__ ei32,
                              int npairs) {
    __shared__ int any;
    if (threadIdx.x == 0) any = 0;
    __syncthreads();
    int found = 0;
    for (int i = threadIdx.x; i < npairs; i += blockDim.x)
        if (ei32[2 * i + 1] != 0u) found = 1;
    if (found) any = 1;   // benign race
    __syncthreads();
    if (threadIdx.x == 0) g_is64 = (any == 0);
}

__device__ __forceinline__ int edge_at(const void* __restrict__ ei, int i) {
    if (g_is64) return (int)((const long long*)ei)[i];
    return ((const int*)ei)[i];
}

// ---------------------------------------------------------------------------
// CSR build: histogram -> block scan -> fill
// ---------------------------------------------------------------------------
__global__ void zero_cnt_kernel(int n) {
    int i = blockIdx.x * blockDim.x + threadIdx.x;
    if (i < n) { g_cnt[i] = 0; g_fill[i] = 0; }
}

__global__ void hist_kernel(const void* __restrict__ ei, int E, int n) {
    int e = blockIdx.x * blockDim.x + threadIdx.x;
    if (e >= E) return;
    unsigned d = min((unsigned)edge_at(ei, E + e), (unsigned)(n - 1));
    atomicAdd(&g_cnt[d], 1);
}

__global__ void __launch_bounds__(SCAN_B) scan1_kernel(int n) {
    __shared__ int sm[SCAN_B];
    int i = blockIdx.x * SCAN_B + threadIdx.x;
    sm[threadIdx.x] = (i < n) ? g_cnt[i] : 0;
    __syncthreads();
    for (int off = SCAN_B / 2; off > 0; off >>= 1) {
        if (threadIdx.x < off) sm[threadIdx.x] += sm[threadIdx.x + off];
        __syncthreads();
    }
    if (threadIdx.x == 0) g_blocksum[blockIdx.x] = sm[0];
}

__global__ void scan2_kernel(int nb, int n, int E) {
    if (threadIdx.x == 0) {
        int run = 0;
        for (int b = 0; b < nb; b++) { g_blockoff[b] = run; run += g_blocksum[b]; }
        g_rowptr[n] = E;
    }
}

__global__ void __launch_bounds__(SCAN_B) scan3_kernel(int n) {
    __shared__ int sm[SCAN_B];
    int i = blockIdx.x * SCAN_B + threadIdx.x;
    int v = (i < n) ? g_cnt[i] : 0;
    sm[threadIdx.x] = v;
    __syncthreads();
    for (int off = 1; off < SCAN_B; off <<= 1) {
        int t = 0;
        if ((int)threadIdx.x >= off) t = sm[threadIdx.x - off];
        __syncthreads();
        if ((int)threadIdx.x >= off) sm[threadIdx.x] += t;
        __syncthreads();
    }
    if (i < n) g_rowptr[i] = g_blockoff[blockIdx.x] + sm[threadIdx.x] - v;
}

__global__ void fill_kernel(const void* __restrict__ ei, int E, int n) {
    int e = blockIdx.x * blockDim.x + threadIdx.x;
    if (e >= E) return;
    unsigned s = min((unsigned)edge_at(ei, e), (unsigned)(n - 1));
    unsigned d = min((unsigned)edge_at(ei, E + e), (unsigned)(n - 1));
    int pos = g_rowptr[d] + atomicAdd(&g_fill[d], 1);
    g_col[pos] = (int)s;
}

// ---------------------------------------------------------------------------
// Gather aggregation: msum[i] = mean over in-neighbors of h[col].
// ---------------------------------------------------------------------------
template <int SRC>
__global__ void __launch_bounds__(256) agg_kernel(const float* __restrict__ x,
                                                  int n) {
    int tid = blockIdx.x * blockDim.x + threadIdx.x;
    int node = tid >> 5;
    if (node >= n) return;
    int lane = tid & 31;
    const float* h = (SRC == 0) ? x : g_h1;
    int beg = g_rowptr[node], end = g_rowptr[node + 1];
    float4 acc = make_float4(0.f, 0.f, 0.f, 0.f);
    int k = beg;
    for (; k + 4 <= end; k += 4) {
        int c0 = g_col[k + 0], c1 = g_col[k + 1];
        int c2 = g_col[k + 2], c3 = g_col[k + 3];
        float4 v0 = *(const float4*)(h + (size_t)c0 * D + lane * 4);
        float4 v1 = *(const float4*)(h + (size_t)c1 * D + lane * 4);
        float4 v2 = *(const float4*)(h + (size_t)c2 * D + lane * 4);
        float4 v3 = *(const float4*)(h + (size_t)c3 * D + lane * 4);
        acc.x += v0.x + v1.x + v2.x + v3.x;
        acc.y += v0.y + v1.y + v2.y + v3.y;
        acc.z += v0.z + v1.z + v2.z + v3.z;
        acc.w += v0.w + v1.w + v2.w + v3.w;
    }
    for (; k < end; ++k) {
        int c = g_col[k];
        float4 v = *(const float4*)(h + (size_t)c * D + lane * 4);
        acc.x += v.x; acc.y += v.y; acc.z += v.z; acc.w += v.w;
    }
    float sc = 1.f / fmaxf((float)(end - beg), 1.f);
    acc.x *= sc; acc.y *= sc; acc.z *= sc; acc.w *= sc;
    *(float4*)(g_msum + (size_t)node * D + lane * 4) = acc;
}

// ---------------------------------------------------------------------------
// SAGE layer via tensor cores (3xTF32): out = relu(msum@Wl + bl + h@Wr)
// Block = 8 warps x 16 nodes = 128 nodes; each warp computes its 16x128 tile.
// Weights staged in SMEM (hi/lo tf32) in four K=64 stages.
// ---------------------------------------------------------------------------
template <int SRC, int OUT>
__global__ void __launch_bounds__(256, 2) sage_mma(
    const float* __restrict__ x, const float* __restrict__ Wl,
    const float* __restrict__ bl, const float* __restrict__ Wr, int n) {
    extern __shared__ uint32_t sw[];
    uint32_t* sWhi = sw;
    uint32_t* sWlo = sw + SM_K * SM_PITCH;

    const int tid = threadIdx.x;
    const int wid = tid >> 5;
    const int lane = tid & 31;
    const int g = lane >> 2;     // group id: row within tile
    const int tig = lane & 3;    // thread in group: k / col selector

    const float* h = (SRC == 0) ? x : g_h1;
    float* out = (OUT == 1) ? g_h1 : g_h2;

    const int wbase = blockIdx.x * 128 + wid * 16;
    const int r0 = min(wbase + g, n - 1);
    const int r1 = min(wbase + g + 8, n - 1);

    // C fragments: 16 n-tiles x 4 regs, initialized with bias
    float c[16][4];
#pragma unroll
    for (int nt = 0; nt < 16; ++nt) {
        int col0 = nt * 8 + tig * 2;
        float b0 = bl[col0], b1 = bl[col0 + 1];
        c[nt][0] = b0; c[nt][1] = b1;
        c[nt][2] = b0; c[nt][3] = b1;
    }

#pragma unroll 1
    for (int pass = 0; pass < 4; ++pass) {
        const float* W = (pass < 2) ? Wl : Wr;
        const float* A = (pass < 2) ? g_msum : h;
        const int k0 = (pass & 1) * SM_K;

        __syncthreads();
        // stage K=64 slab of W, split hi/lo tf32
        for (int idx = tid; idx < SM_K * 128; idx += 256) {
            int k = idx >> 7, nn = idx & 127;
            float w = W[(k0 + k) * 128 + nn];
            uint32_t hi = f2tf32(w);
            float lo = w - __uint_as_float(hi);
            sWhi[k * SM_PITCH + nn] = hi;
            sWlo[k * SM_PITCH + nn] = f2tf32(lo);
        }
        __syncthreads();

        const float* a0p = A + (size_t)r0 * D + k0;
        const float* a1p = A + (size_t)r1 * D + k0;

#pragma unroll
        for (int ks = 0; ks < 8; ++ks) {
            const int kc = ks * 8 + tig;
            float f0 = a0p[kc], f1 = a1p[kc];
            float f2v = a0p[kc + 4], f3 = a1p[kc + 4];
            uint32_t ah0 = f2tf32(f0), ah1 = f2tf32(f1);
            uint32_t ah2 = f2tf32(f2v), ah3 = f2tf32(f3);
            uint32_t al0 = f2tf32(f0 - __uint_as_float(ah0));
            uint32_t al1 = f2tf32(f1 - __uint_as_float(ah1));
            uint32_t al2 = f2tf32(f2v - __uint_as_float(ah2));
            uint32_t al3 = f2tf32(f3 - __uint_as_float(ah3));

            const int kb = (ks * 8 + tig) * SM_PITCH + g;
#pragma unroll
            for (int nt = 0; nt < 16; ++nt) {
                const int base = kb + nt * 8;
                uint32_t bh0 = sWhi[base];
                uint32_t bh1 = sWhi[base + 4 * SM_PITCH];
                uint32_t bl0 = sWlo[base];
                uint32_t bl1 = sWlo[base + 4 * SM_PITCH];
                mma_tf32(c[nt][0], c[nt][1], c[nt][2], c[nt][3],
                         ah0, ah1, ah2, ah3, bh0, bh1);
                mma_tf32(c[nt][0], c[nt][1], c[nt][2], c[nt][3],
                         ah0, ah1, ah2, ah3, bl0, bl1);
                mma_tf32(c[nt][0], c[nt][1], c[nt][2], c[nt][3],
                         al0, al1, al2, al3, bh0, bh1);
            }
        }
    }

    // epilogue: relu + store (rows g and g+8)
    const int row0 = wbase + g;
    const int row1 = wbase + g + 8;
    if (row0 < n) {
        float* o = out + (size_t)row0 * D + tig * 2;
#pragma unroll
        for (int nt = 0; nt < 16; ++nt)
            *(float2*)(o + nt * 8) =
                make_float2(fmaxf(c[nt][0], 0.f), fmaxf(c[nt][1], 0.f));
    }
    if (row1 < n) {
        float* o = out + (size_t)row1 * D + tig * 2;
#pragma unroll
        for (int nt = 0; nt < 16; ++nt)
            *(float2*)(o + nt * 8) =
                make_float2(fmaxf(c[nt][2], 0.f), fmaxf(c[nt][3], 0.f));
    }
}

// ---------------------------------------------------------------------------
// lin0: t = relu(g_h2 @ W0 + b0) -> g_msum[node*64 + col]  (SIMT FFMA2)
// ---------------------------------------------------------------------------
__global__ void __launch_bounds__(256) lin0_kernel(
    const float* __restrict__ W0, const float* __restrict__ b0, int n) {
    __shared__ float sW0[D * 32];
    __shared__ float sb[32];

    const int j0 = blockIdx.y * 32;
    for (int idx = threadIdx.x; idx < D * 32; idx += 256) {
        int k = idx >> 5, jj = idx & 31;
        sW0[idx] = W0[k * 64 + j0 + jj];
    }
    if (threadIdx.x < 32) sb[threadIdx.x] = b0[j0 + threadIdx.x];
    __syncthreads();

    int nd[4];
    const float4* hp[4];
#pragma unroll
    for (int i = 0; i < 4; i++) {
        nd[i] = blockIdx.x * 1024 + threadIdx.x + i * 256;
        int c = min(nd[i], n - 1);
        hp[i] = (const float4*)(g_h2 + (size_t)c * D);
    }

    unsigned long long acc[4][16];
#pragma unroll
    for (int p = 0; p < 16; p++) {
        unsigned long long b = pack2(sb[2 * p], sb[2 * p + 1]);
#pragma unroll
        for (int i = 0; i < 4; i++) acc[i][p] = b;
    }

    for (int k4 = 0; k4 < 32; ++k4) {
        float ar[4][4];
#pragma unroll
        for (int i = 0; i < 4; i++) {
            float4 q = hp[i][k4];
            ar[i][0] = q.x; ar[i][1] = q.y; ar[i][2] = q.z; ar[i][3] = q.w;
        }
#pragma unroll
        for (int kk = 0; kk < 4; ++kk) {
            const int kbase = (k4 * 4 + kk) * 32;
            ulonglong2 w0 = *(const ulonglong2*)&sW0[kbase + 0];
            ulonglong2 w1 = *(const ulonglong2*)&sW0[kbase + 4];
            ulonglong2 w2 = *(const ulonglong2*)&sW0[kbase + 8];
            ulonglong2 w3 = *(const ulonglong2*)&sW0[kbase + 12];
            ulonglong2 w4 = *(const ulonglong2*)&sW0[kbase + 16];
            ulonglong2 w5 = *(const ulonglong2*)&sW0[kbase + 20];
            ulonglong2 w6 = *(const ulonglong2*)&sW0[kbase + 24];
            ulonglong2 w7 = *(const ulonglong2*)&sW0[kbase + 28];
#pragma unroll
            for (int i = 0; i < 4; i++) {
                unsigned long long pr = pack2(ar[i][kk], ar[i][kk]);
                ffma2(acc[i][0],  pr, w0.x);
                ffma2(acc[i][1],  pr, w0.y);
                ffma2(acc[i][2],  pr, w1.x);
                ffma2(acc[i][3],  pr, w1.y);
                ffma2(acc[i][4],  pr, w2.x);
                ffma2(acc[i][5],  pr, w2.y);
                ffma2(acc[i][6],  pr, w3.x);
                ffma2(acc[i][7],  pr, w3.y);
                ffma2(acc[i][8],  pr, w4.x);
                ffma2(acc[i][9],  pr, w4.y);
                ffma2(acc[i][10], pr, w5.x);
                ffma2(acc[i][11], pr, w5.y);
                ffma2(acc[i][12], pr, w6.x);
                ffma2(acc[i][13], pr, w6.y);
                ffma2(acc[i][14], pr, w7.x);
                ffma2(acc[i][15], pr, w7.y);
            }
        }
    }

#pragma unroll
    for (int i = 0; i < 4; i++) {
        if (nd[i] < n) {
            float4* o = (float4*)(g_msum + (size_t)nd[i] * 64 + j0);
#pragma unroll
            for (int q = 0; q < 8; ++q) {
                float2 a = unpack2(acc[i][q * 2 + 0]);
                float2 b = unpack2(acc[i][q * 2 + 1]);
                o[q] = make_float4(fmaxf(a.x, 0.f), fmaxf(a.y, 0.f),
                                   fmaxf(b.x, 0.f), fmaxf(b.y, 0.f));
            }
        }
    }
}

// ---------------------------------------------------------------------------
// lin1: out = relu(t @ W1 + b1), t = g_msum[node*64 .. +64]
// ---------------------------------------------------------------------------
__global__ void __launch_bounds__(256) lin1_kernel(
    const float* __restrict__ W1, const float* __restrict__ b1,
    float* __restrict__ out, int n) {
    __shared__ float sW1[64 * 8];
    __shared__ float sb1[8];
    for (int idx = threadIdx.x; idx < 64 * 8; idx += 256) sW1[idx] = W1[idx];
    if (threadIdx.x < 8) sb1[threadIdx.x] = b1[threadIdx.x];
    __syncthreads();

    const int n0 = blockIdx.x * 256 + threadIdx.x;
    const int c0 = min(n0, n - 1);
    const float4* tp = (const float4*)(g_msum + (size_t)c0 * 64);

    unsigned long long o2[4];
#pragma unroll
    for (int p = 0; p < 4; p++) o2[p] = pack2(sb1[2 * p], sb1[2 * p + 1]);

#pragma unroll
    for (int k4 = 0; k4 < 16; ++k4) {
        float4 tv = tp[k4];
        float r[4] = {tv.x, tv.y, tv.z, tv.w};
#pragma unroll
        for (int kk = 0; kk < 4; ++kk) {
            const int kbase = (k4 * 4 + kk) * 8;
            ulonglong2 wA = *(const ulonglong2*)&sW1[kbase + 0];
            ulonglong2 wB = *(const ulonglong2*)&sW1[kbase + 4];
            unsigned long long pr = pack2(r[kk], r[kk]);
            ffma2(o2[0], pr, wA.x);
            ffma2(o2[1], pr, wA.y);
            ffma2(o2[2], pr, wB.x);
            ffma2(o2[3], pr, wB.y);
        }
    }

    if (n0 < n) {
        float4* op = (float4*)(out + (size_t)n0 * 8);
        float2 a = unpack2(o2[0]), b = unpack2(o2[1]);
        float2 c = unpack2(o2[2]), dd = unpack2(o2[3]);
        op[0] = make_float4(fmaxf(a.x, 0.f), fmaxf(a.y, 0.f),
                            fmaxf(b.x, 0.f), fmaxf(b.y, 0.f));
        op[1] = make_float4(fmaxf(c.x, 0.f), fmaxf(c.y, 0.f),
                            fmaxf(dd.x, 0.f), fmaxf(dd.y, 0.f));
    }
}

// ---------------------------------------------------------------------------
// Launcher (no allocation, graph-capturable)
// ---------------------------------------------------------------------------
extern "C" void kernel_launch(void* const* d_in, const int* in_sizes, int n_in,
                              void* d_out, int out_size) {
    const float* x    = (const float*)d_in[0];
    const void*  ei   = d_in[1];
    const float* s0Wl = (const float*)d_in[2];
    const float* s0bl = (const float*)d_in[3];
    const float* s0Wr = (const float*)d_in[4];
    const float* s1Wl = (const float*)d_in[5];
    const float* s1bl = (const float*)d_in[6];
    const float* s1Wr = (const float*)d_in[7];
    const float* l0W  = (const float*)d_in[8];
    const float* l0b  = (const float*)d_in[9];
    const float* l1W  = (const float*)d_in[10];
    const float* l1b  = (const float*)d_in[11];
    float* out = (float*)d_out;

    const int N = in_sizes[0] / D;
    const int E = in_sizes[1] / 2;
    const int NB = (N + SCAN_B - 1) / SCAN_B;

    cudaFuncSetAttribute(sage_mma<0, 1>,
                         cudaFuncAttributeMaxDynamicSharedMemorySize, SM_BYTES);
    cudaFuncSetAttribute(sage_mma<1, 2>,
                         cudaFuncAttributeMaxDynamicSharedMemorySize, SM_BYTES);

    detect_kernel<<<1, 256>>>((const unsigned int*)ei, 2048);

    // CSR build (once per launch; shared by both layers)
    zero_cnt_kernel<<<(N + 255) / 256, 256>>>(N);
    hist_kernel<<<(E + 255) / 256, 256>>>(ei, E, N);
    scan1_kernel<<<NB, SCAN_B>>>(N);
    scan2_kernel<<<1, 32>>>(NB, N, E);
    scan3_kernel<<<NB, SCAN_B>>>(N);
    fill_kernel<<<(E + 255) / 256, 256>>>(ei, E, N);

    const int agg_blocks = (int)(((long long)N * 32 + 255) / 256);
    const int mma_blocks = (N + 127) / 128;
    dim3 lgrid((N + 1023) / 1024, 2);

    // layer 0
    agg_kernel<0><<<agg_blocks, 256>>>(x, N);
    sage_mma<0, 1><<<mma_blocks, 256, SM_BYTES>>>(x, s0Wl, s0bl, s0Wr, N);

    // layer 1
    agg_kernel<1><<<agg_blocks, 256>>>(x, N);
    sage_mma<1, 2><<<mma_blocks, 256, SM_BYTES>>>(x, s1Wl, s1bl, s1Wr, N);

    // MLP head
    lin0_kernel<<<lgrid, 256>>>(l0W, l0b, N);
    lin1_kernel<<<(N + 255) / 256, 256>>>(l1W, l1b, out, N);
}